// round 8
// baseline (speedup 1.0000x reference)
#include <cuda_runtime.h>
#include <cuda_fp16.h>
#include <mma.h>

using namespace nvcuda;

// Problem constants
#define B_WIN   4096
#define NTOK    49
#define CDIM    384
#define NHEADS  12
#define HDIM    32
#define NWIN    1024
#define SCALE_Q 0.17677669529663687f  // 32^-0.5

// Precomputed-weight globals (~1.5 MB)
__device__ __align__(256) __half g_wqkv[NHEADS * 96 * CDIM];  // head-permuted qkv_w
__device__ __align__(256) __half g_wpj_h[CDIM * CDIM];        // proj_w hi
__device__ __align__(256) __half g_wpj_l[CDIM * CDIM];        // proj_w lo

// Shared memory layout (byte offsets)
#define SM_XH   0          // Xh: 64 x 392 half = 50176
#define SM_QST  50176      // multiplexed: GEMM stage 64x196 f32 (50176) |
                           //   S 2x64x68 f32 (34816) + Sh 2x64x72 half (18432) = 53248
#define SM_QKV  103424     // qkv pair: 2 heads x 3 x 64x40 half = 30720
#define SM_OH   134144     // Oh: 64 x 392 half = 50176
#define SM_RB   184320     // rpb all heads: 12 x 169 f32 = 8112
#define SM_PAR  192432     // qkv_b(1152) + proj_b(384) + lamb(12) f32 = 6192
#define SMEM_BYTES 198624

#define XLD   392
#define KVLD  40
#define SLD   68           // S fp32 ld
#define SHLD  72           // Sh fp16 ld
#define QLD   196          // GEMM staging ld (floats)
#define PQLD  100          // proj staging ld (floats)
#define SH_OFF 34816       // byte offset of Sh inside QST region

// ---------------------------------------------------------------------------
// Weight precompute kernels
// ---------------------------------------------------------------------------
__global__ void prep_qkv_w(const float* __restrict__ qkv_w)
{
    int idx = blockIdx.x * 256 + threadIdx.x;
    if (idx < NHEADS * 96 * CDIM) {
        int h   = idx / (96 * CDIM);
        int rem = idx % (96 * CDIM);
        int j   = rem / CDIM;
        int k   = rem % CDIM;
        int g   = (j >> 5) * CDIM + h * HDIM + (j & 31);
        g_wqkv[idx] = __float2half_rn(qkv_w[(size_t)g * CDIM + k]);
    }
}

__global__ void prep_proj_w(const float* __restrict__ proj_w)
{
    int idx = blockIdx.x * 256 + threadIdx.x;
    if (idx < CDIM * CDIM) {
        float v = proj_w[idx];
        __half hi = __float2half_rn(v);
        g_wpj_h[idx] = hi;
        g_wpj_l[idx] = __float2half_rn(v - __half2float(hi));
    }
}

// ---------------------------------------------------------------------------
// Fused window attention: one block per window, 384 threads.
// Head-pair groups; GEMM B-operands streamed directly from global (L2).
// ---------------------------------------------------------------------------
__global__ void __launch_bounds__(384, 1)
winattn_kernel(const float* __restrict__ x,
               const float* __restrict__ mask,
               const float* __restrict__ qkv_b,
               const float* __restrict__ proj_b,
               const float* __restrict__ rpb,
               const float* __restrict__ lamb,
               float* __restrict__ out)
{
    extern __shared__ __align__(16) char smraw[];
    __half* Xh  = (__half*)(smraw + SM_XH);
    float*  Sf  = (float*)(smraw + SM_QST);            // also GEMM/proj staging
    __half* Sh  = (__half*)(smraw + SM_QST + SH_OFF);
    __half* qkv = (__half*)(smraw + SM_QKV);           // [hh][q|k|v][64][40]
    __half* Oh  = (__half*)(smraw + SM_OH);
    float*  rb  = (float*)(smraw + SM_RB);
    float*  par = (float*)(smraw + SM_PAR);

    const int tid = threadIdx.x;
    const int wp  = tid >> 5;
    const int l   = tid & 31;
    const int w   = blockIdx.x;

    // ---- init: X fp16, zero pads, rb, params ----
    for (int t = tid; t < 49 * 96; t += 384) {
        int r = t / 96, c4 = (t % 96) * 4;
        float4 v = *(const float4*)&x[((size_t)w * NTOK + r) * CDIM + c4];
        *(__half2*)&Xh[r * XLD + c4]     = __floats2half2_rn(v.x, v.y);
        *(__half2*)&Xh[r * XLD + c4 + 2] = __floats2half2_rn(v.z, v.w);
    }
    for (int t = tid; t < 15 * 196; t += 384) {        // zero pad rows 49..63
        int r = 49 + t / 196, c2 = (t % 196) * 2;
        __half2 z = __floats2half2_rn(0.0f, 0.0f);
        *(__half2*)&Xh[r * XLD + c2] = z;
        *(__half2*)&Oh[r * XLD + c2] = z;
    }
    for (int t = tid; t < 1920; t += 384)              // zero qkv fully
        ((int4*)qkv)[t] = make_int4(0, 0, 0, 0);
    for (int t = tid; t < NHEADS * 169; t += 384)
        rb[t] = rpb[(t % 169) * NHEADS + (t / 169)];
    for (int t = tid; t < 1548; t += 384)
        par[t] = (t < 1152) ? qkv_b[t] : (t < 1536 ? proj_b[t - 1152] : lamb[t - 1536]);
    __syncthreads();

    const float* mrow = mask + (size_t)(w & (NWIN - 1)) * (NTOK * NTOK);
    const int mrow0 = (wp & 1) * 32;     // GEMM: 2 m-tiles per warp
    const int ngq   = (wp >> 1) * 32;    // qkv GEMM: 32-col group (0..160)

    // =============== 6 groups of 2 heads ===============
    for (int g = 0; g < 6; ++g) {
        const int h0 = 2 * g;

        // ---- QKV GEMM: 64x192 = Xh @ Wg^T, B direct from global, sync-free ----
        {
            const __half* Wg = g_wqkv + (size_t)h0 * (96 * CDIM);
            wmma::fragment<wmma::accumulator, 16, 16, 16, float> acc[2][2];
#pragma unroll
            for (int i = 0; i < 2; ++i)
#pragma unroll
                for (int j = 0; j < 2; ++j) wmma::fill_fragment(acc[i][j], 0.0f);

#pragma unroll 4
            for (int ks = 0; ks < 24; ++ks) {
                wmma::fragment<wmma::matrix_a, 16, 16, 16, __half, wmma::row_major> a0, a1;
                wmma::load_matrix_sync(a0, &Xh[mrow0 * XLD + ks * 16], XLD);
                wmma::load_matrix_sync(a1, &Xh[(mrow0 + 16) * XLD + ks * 16], XLD);
                wmma::fragment<wmma::matrix_b, 16, 16, 16, __half, wmma::col_major> b0, b1;
                wmma::load_matrix_sync(b0, Wg + (size_t)ngq * CDIM + ks * 16, CDIM);
                wmma::load_matrix_sync(b1, Wg + (size_t)(ngq + 16) * CDIM + ks * 16, CDIM);
                wmma::mma_sync(acc[0][0], a0, b0, acc[0][0]);
                wmma::mma_sync(acc[0][1], a0, b1, acc[0][1]);
                wmma::mma_sync(acc[1][0], a1, b0, acc[1][0]);
                wmma::mma_sync(acc[1][1], a1, b1, acc[1][1]);
            }
#pragma unroll
            for (int i = 0; i < 2; ++i)
#pragma unroll
                for (int j = 0; j < 2; ++j)
                    wmma::store_matrix_sync(&Sf[(mrow0 + i * 16) * QLD + ngq + j * 16],
                                            acc[i][j], QLD, wmma::mem_row_major);
        }
        __syncthreads();

        // ---- bias + q-scale + convert -> qkv fp16 ----
        for (int t = tid; t < 49 * 192; t += 384) {
            int r = t / 192, cc = t % 192;
            int hh = cc / 96, c2 = cc % 96, which = c2 >> 5, d = c2 & 31;
            float vv = Sf[r * QLD + cc] + par[which * CDIM + (h0 + hh) * HDIM + d];
            if (which == 0) vv *= SCALE_Q;
            qkv[hh * 7680 + which * 2560 + r * KVLD + d] = __float2half_rn(vv);
        }
        __syncthreads();

        // ---- S = q @ k^T : 32 tiles over 12 warps ----
        for (int t = wp; t < 32; t += 12) {
            int hh = t >> 4, mi = (t >> 2) & 3, nj = t & 3;
            const __half* qh = qkv + hh * 7680;
            const __half* kh = qh + 2560;
            wmma::fragment<wmma::accumulator, 16, 16, 16, float> sacc;
            wmma::fill_fragment(sacc, 0.0f);
#pragma unroll
            for (int ks = 0; ks < 2; ++ks) {
                wmma::fragment<wmma::matrix_a, 16, 16, 16, __half, wmma::row_major> a1;
                wmma::fragment<wmma::matrix_b, 16, 16, 16, __half, wmma::col_major> b1;
                wmma::load_matrix_sync(a1, &qh[mi * 16 * KVLD + ks * 16], KVLD);
                wmma::load_matrix_sync(b1, &kh[nj * 16 * KVLD + ks * 16], KVLD);
                wmma::mma_sync(sacc, a1, b1, sacc);
            }
            wmma::store_matrix_sync(&Sf[hh * 4352 + mi * 16 * SLD + nj * 16],
                                    sacc, SLD, wmma::mem_row_major);
        }
        __syncthreads();

        // ---- softmax (+rpb+mask, lamb rescale) -> Sh fp16; zero pad rows ----
        for (int i2 = wp; i2 < 128; i2 += 12) {
            int hh = i2 >> 6, i = i2 & 63;
            __half* ShH = Sh + hh * 4608;
            if (i < NTOK) {
                const float lam1 = 1.0f + par[1536 + h0 + hh];
                const float invn = 1.0f / (float)NTOK;
                const float* rbh = rb + (h0 + hh) * 169;
                const int i7 = i / 7, im = i - i7 * 7;
                const int j0 = l, j1 = l + 32;
                const int r0 = (i7 - j0 / 7 + 6) * 13 + (im - j0 % 7 + 6);
                float s0 = Sf[hh * 4352 + i * SLD + j0] + rbh[r0] + mrow[i * NTOK + j0];
                float s1 = -1e30f;
                if (j1 < NTOK) {
                    const int r1 = (i7 - j1 / 7 + 6) * 13 + (im - j1 % 7 + 6);
                    s1 = Sf[hh * 4352 + i * SLD + j1] + rbh[r1] + mrow[i * NTOK + j1];
                }
                float mx = fmaxf(s0, s1);
#pragma unroll
                for (int off = 16; off > 0; off >>= 1)
                    mx = fmaxf(mx, __shfl_xor_sync(0xffffffffu, mx, off));
                float e0 = __expf(s0 - mx);
                float e1 = (j1 < NTOK) ? __expf(s1 - mx) : 0.0f;
                float sm = e0 + e1;
#pragma unroll
                for (int off = 16; off > 0; off >>= 1)
                    sm += __shfl_xor_sync(0xffffffffu, sm, off);
                const float inv = 1.0f / sm;
                ShH[i * SHLD + j0] = __float2half_rn(invn + (e0 * inv - invn) * lam1);
                ShH[i * SHLD + j1] = (j1 < NTOK)
                    ? __float2half_rn(invn + (e1 * inv - invn) * lam1)
                    : __float2half_rn(0.0f);
            } else {
                ShH[i * SHLD + l]      = __float2half_rn(0.0f);
                ShH[i * SHLD + l + 32] = __float2half_rn(0.0f);
            }
        }
        __syncthreads();

        // ---- O = attn @ v : 16 tiles over 12 warps ----
        for (int t = wp; t < 16; t += 12) {
            int hh = t >> 3, mi = (t >> 1) & 3, nj = t & 1;
            const __half* ShH = Sh + hh * 4608;
            const __half* vhh = qkv + hh * 7680 + 5120;
            wmma::fragment<wmma::accumulator, 16, 16, 16, float> oacc;
            wmma::fill_fragment(oacc, 0.0f);
#pragma unroll
            for (int ks = 0; ks < 4; ++ks) {
                wmma::fragment<wmma::matrix_a, 16, 16, 16, __half, wmma::row_major> a1;
                wmma::fragment<wmma::matrix_b, 16, 16, 16, __half, wmma::row_major> b1;
                wmma::load_matrix_sync(a1, &ShH[mi * 16 * SHLD + ks * 16], SHLD);
                wmma::load_matrix_sync(b1, &vhh[ks * 16 * KVLD + nj * 16], KVLD);
                wmma::mma_sync(oacc, a1, b1, oacc);
            }
            wmma::store_matrix_sync(&Sf[hh * 4352 + mi * 16 * SLD + nj * 16],
                                    oacc, SLD, wmma::mem_row_major);
        }
        __syncthreads();

        // ---- convert O -> Oh ----
        for (int t = tid; t < 49 * 64; t += 384) {
            int r = t >> 6, cc = t & 63, hh = cc >> 5, d = cc & 31;
            Oh[r * XLD + (h0 + hh) * HDIM + d] = __float2half_rn(Sf[hh * 4352 + r * SLD + d]);
        }
        __syncthreads();
    }

    // =============== proj: out = Oh @ proj_w^T + b (hi/lo, B from global) ===============
    for (int p = 0; p < 4; ++p) {
        const int nc = p * 96 + (wp >> 1) * 16;   // global col of this warp's 16-col tile
        wmma::fragment<wmma::accumulator, 16, 16, 16, float> acc2[2];
        wmma::fill_fragment(acc2[0], 0.0f);
        wmma::fill_fragment(acc2[1], 0.0f);

#pragma unroll 4
        for (int ks = 0; ks < 24; ++ks) {
            wmma::fragment<wmma::matrix_a, 16, 16, 16, __half, wmma::row_major> a0, a1;
            wmma::load_matrix_sync(a0, &Oh[mrow0 * XLD + ks * 16], XLD);
            wmma::load_matrix_sync(a1, &Oh[(mrow0 + 16) * XLD + ks * 16], XLD);
            wmma::fragment<wmma::matrix_b, 16, 16, 16, __half, wmma::col_major> bh, bl;
            wmma::load_matrix_sync(bh, g_wpj_h + (size_t)nc * CDIM + ks * 16, CDIM);
            wmma::load_matrix_sync(bl, g_wpj_l + (size_t)nc * CDIM + ks * 16, CDIM);
            wmma::mma_sync(acc2[0], a0, bh, acc2[0]);
            wmma::mma_sync(acc2[0], a0, bl, acc2[0]);
            wmma::mma_sync(acc2[1], a1, bh, acc2[1]);
            wmma::mma_sync(acc2[1], a1, bl, acc2[1]);
        }
        const int lc = nc - p * 96;
        wmma::store_matrix_sync(&Sf[mrow0 * PQLD + lc], acc2[0], PQLD, wmma::mem_row_major);
        wmma::store_matrix_sync(&Sf[(mrow0 + 16) * PQLD + lc], acc2[1], PQLD, wmma::mem_row_major);
        __syncthreads();

        for (int t = tid; t < 49 * 96; t += 384) {
            int r = t / 96, cc = t % 96;
            out[((size_t)w * NTOK + r) * CDIM + p * 96 + cc] = Sf[r * PQLD + cc] + par[1152 + p * 96 + cc];
        }
        __syncthreads();
    }
}

// ---------------------------------------------------------------------------
// Host: bind inputs by element count (all 8 sizes distinct)
// ---------------------------------------------------------------------------
extern "C" void kernel_launch(void* const* d_in, const int* in_sizes, int n_in,
                              void* d_out, int out_size)
{
    const float *x = 0, *mask = 0, *qkv_w = 0, *qkv_b = 0;
    const float *proj_w = 0, *proj_b = 0, *rpb = 0, *lamb = 0;

    for (int i = 0; i < n_in; ++i) {
        const float* p = (const float*)d_in[i];
        switch (in_sizes[i]) {
            case 77070336: x      = p; break;
            case 2458624:  mask   = p; break;
            case 442368:   qkv_w  = p; break;
            case 1152:     qkv_b  = p; break;
            case 147456:   proj_w = p; break;
            case 384:      proj_b = p; break;
            case 2028:     rpb    = p; break;
            case 12:       lamb   = p; break;
            default: break;
        }
    }
    if (!x || !mask || !qkv_w || !qkv_b || !proj_w || !proj_b || !rpb || !lamb) {
        x      = (const float*)d_in[0];
        mask   = (const float*)d_in[1];
        qkv_w  = (const float*)d_in[2];
        qkv_b  = (const float*)d_in[3];
        proj_w = (const float*)d_in[4];
        proj_b = (const float*)d_in[5];
        rpb    = (const float*)d_in[6];
        lamb   = (const float*)d_in[7];
    }

    prep_qkv_w<<<(NHEADS * 96 * CDIM + 255) / 256, 256>>>(qkv_w);
    prep_proj_w<<<(CDIM * CDIM + 255) / 256, 256>>>(proj_w);

    cudaFuncSetAttribute(winattn_kernel,
                         cudaFuncAttributeMaxDynamicSharedMemorySize, SMEM_BYTES);
    winattn_kernel<<<B_WIN, 384, SMEM_BYTES>>>(
        x, mask, qkv_b, proj_b, rpb, lamb, (float*)d_out);
}

// round 9
// speedup vs baseline: 1.6583x; 1.6583x over previous
#include <cuda_runtime.h>
#include <cuda_fp16.h>
#include <mma.h>

using namespace nvcuda;

// Problem constants
#define B_WIN   4096
#define NTOK    49
#define CDIM    384
#define NHEADS  12
#define HDIM    32
#define NWIN    1024
#define SCALE_Q 0.17677669529663687f  // 32^-0.5

// Precomputed-weight globals (~1.5 MB)
__device__ __align__(256) __half g_wqkv[NHEADS * 96 * CDIM];  // head-permuted qkv_w
__device__ __align__(256) __half g_wpj_h[CDIM * CDIM];        // proj_w hi
__device__ __align__(256) __half g_wpj_l[CDIM * CDIM];        // proj_w lo

// Shared memory layout (byte offsets)
#define SM_XH   0        // Xh: 64 x 392 half = 50176
#define SM_SF   50176    // multiplexed: GEMM staging 64x196 f32 (50176) |
                         //   S 2x64x68 f32 (34816) + Sh 2x64x72 half (18432) |
                         //   proj staging 64x100 f32
#define SM_WB   103424   // W staging 2 x 192 x 72 half (55296) | qkv 2x7680 half (30720)
#define SM_OH   158720   // Oh: 64 x 392 half = 50176
#define SM_MS   208896   // mask: 49 x 50 f32 = 9800
#define SM_RB   218696   // rpb all heads fp16: 12 x 169 = 4056
#define SM_PAR  222752   // qkv_b(1152)+proj_b(384)+lamb(12) f32 = 6192
#define SMEM_BYTES 228944

#define XLD   392        // Xh/Oh ld (halves)
#define WLD   72         // W staging ld (halves)
#define WBUF  13824      // halves per W buffer (192*72)
#define KVLD  40         // qkv ld (halves)
#define QLD   196        // GEMM staging ld (floats)
#define SLD   68         // S f32 ld
#define SHLD  72         // Sh ld (halves)
#define PQLD  100        // proj staging ld (floats)
#define SH_OFF 34816     // byte offset of Sh inside SF region
#define PLOFF 6912       // proj lo offset within a W buffer (halves)

// ---------------------------------------------------------------------------
__global__ void prep_qkv_w(const float* __restrict__ qkv_w)
{
    int idx = blockIdx.x * 256 + threadIdx.x;
    if (idx < NHEADS * 96 * CDIM) {
        int h   = idx / (96 * CDIM);
        int rem = idx % (96 * CDIM);
        int j   = rem / CDIM;
        int k   = rem % CDIM;
        int g   = (j >> 5) * CDIM + h * HDIM + (j & 31);
        g_wqkv[idx] = __float2half_rn(qkv_w[(size_t)g * CDIM + k]);
    }
}

__global__ void prep_proj_w(const float* __restrict__ proj_w)
{
    int idx = blockIdx.x * 256 + threadIdx.x;
    if (idx < CDIM * CDIM) {
        float v = proj_w[idx];
        __half hi = __float2half_rn(v);
        g_wpj_h[idx] = hi;
        g_wpj_l[idx] = __float2half_rn(v - __half2float(hi));
    }
}

// ---------------------------------------------------------------------------
// Fused window attention: one block per window, 384 threads, head-pair groups,
// double-buffered smem weight staging (no global-B fragment loads).
// ---------------------------------------------------------------------------
__global__ void __launch_bounds__(384, 1)
winattn_kernel(const float* __restrict__ x,
               const float* __restrict__ mask,
               const float* __restrict__ qkv_b,
               const float* __restrict__ proj_b,
               const float* __restrict__ rpb,
               const float* __restrict__ lamb,
               float* __restrict__ out)
{
    extern __shared__ __align__(16) char smraw[];
    __half* Xh  = (__half*)(smraw + SM_XH);
    float*  Sf  = (float*)(smraw + SM_SF);
    __half* Sh  = (__half*)(smraw + SM_SF + SH_OFF);
    __half* WB  = (__half*)(smraw + SM_WB);
    __half* qkv = (__half*)(smraw + SM_WB);            // aliases WB (phase-disjoint)
    __half* Oh  = (__half*)(smraw + SM_OH);
    float*  ms  = (float*)(smraw + SM_MS);
    __half* rb  = (__half*)(smraw + SM_RB);
    float*  par = (float*)(smraw + SM_PAR);

    const int tid = threadIdx.x;
    const int wp  = tid >> 5;
    const int l   = tid & 31;
    const int w   = blockIdx.x;

    // ---- init ----
    for (int t = tid; t < 49 * 96; t += 384) {
        int r = t / 96, c4 = (t % 96) * 4;
        float4 v = *(const float4*)&x[((size_t)w * NTOK + r) * CDIM + c4];
        *(__half2*)&Xh[r * XLD + c4]     = __floats2half2_rn(v.x, v.y);
        *(__half2*)&Xh[r * XLD + c4 + 2] = __floats2half2_rn(v.z, v.w);
    }
    for (int t = tid; t < 15 * 196; t += 384) {        // zero pad rows 49..63
        int r = 49 + t / 196, c2 = (t % 196) * 2;
        __half2 z = __floats2half2_rn(0.0f, 0.0f);
        *(__half2*)&Xh[r * XLD + c2] = z;
        *(__half2*)&Oh[r * XLD + c2] = z;
    }
    {
        const float* mrow = mask + (size_t)(w & (NWIN - 1)) * (NTOK * NTOK);
        for (int t = tid; t < NTOK * NTOK; t += 384)
            ms[(t / 49) * 50 + (t % 49)] = mrow[t];
    }
    for (int t = tid; t < NHEADS * 169; t += 384)
        rb[t] = __float2half_rn(rpb[(t % 169) * NHEADS + (t / 169)]);
    for (int t = tid; t < 1548; t += 384)
        par[t] = (t < 1152) ? qkv_b[t] : (t < 1536 ? proj_b[t - 1152] : lamb[t - 1536]);
    __syncthreads();

    const int mrow0 = (wp & 1) * 32;     // GEMM m-base (2 x 16-row frags)
    const int ngq   = (wp >> 1) * 32;    // QKV GEMM n-base (6 groups of 32)

    // per-thread staging map for 192x64-half chunks (1536 int4, 4/thread)
    int sj[4], sk[4];
#pragma unroll
    for (int i = 0; i < 4; ++i) {
        int v = tid + i * 384;
        sj[i] = v >> 3;
        sk[i] = (v & 7) << 3;
    }

    // =============== 6 groups of 2 heads ===============
    for (int g = 0; g < 6; ++g) {
        const int h0 = 2 * g;
        const __half* Wg = g_wqkv + (size_t)h0 * (96 * CDIM);  // 192 contiguous rows

        // ---- QKV GEMM: 64x192 = Xh @ Wg^T, Kc=64, double buffered ----
        wmma::fragment<wmma::accumulator, 16, 16, 16, float> acc[2][2];
#pragma unroll
        for (int i = 0; i < 2; ++i)
#pragma unroll
            for (int j = 0; j < 2; ++j) wmma::fill_fragment(acc[i][j], 0.0f);

        int4 st[4];
#pragma unroll
        for (int i = 0; i < 4; ++i)
            st[i] = *(const int4*)(Wg + (size_t)sj[i] * CDIM + sk[i]);
#pragma unroll
        for (int i = 0; i < 4; ++i)
            *(int4*)(WB + sj[i] * WLD + sk[i]) = st[i];
        __syncthreads();

        for (int c = 0; c < 6; ++c) {
            if (c < 5) {
#pragma unroll
                for (int i = 0; i < 4; ++i)
                    st[i] = *(const int4*)(Wg + (size_t)sj[i] * CDIM + (c + 1) * 64 + sk[i]);
            }
            const __half* Wc = WB + (c & 1) * WBUF;
#pragma unroll
            for (int ks = 0; ks < 4; ++ks) {
                wmma::fragment<wmma::matrix_a, 16, 16, 16, __half, wmma::row_major> a0, a1;
                wmma::load_matrix_sync(a0, &Xh[mrow0 * XLD + c * 64 + ks * 16], XLD);
                wmma::load_matrix_sync(a1, &Xh[(mrow0 + 16) * XLD + c * 64 + ks * 16], XLD);
                wmma::fragment<wmma::matrix_b, 16, 16, 16, __half, wmma::col_major> b0, b1;
                wmma::load_matrix_sync(b0, &Wc[ngq * WLD + ks * 16], WLD);
                wmma::load_matrix_sync(b1, &Wc[(ngq + 16) * WLD + ks * 16], WLD);
                wmma::mma_sync(acc[0][0], a0, b0, acc[0][0]);
                wmma::mma_sync(acc[0][1], a0, b1, acc[0][1]);
                wmma::mma_sync(acc[1][0], a1, b0, acc[1][0]);
                wmma::mma_sync(acc[1][1], a1, b1, acc[1][1]);
            }
            if (c < 5) {
#pragma unroll
                for (int i = 0; i < 4; ++i)
                    *(int4*)(WB + ((c + 1) & 1) * WBUF + sj[i] * WLD + sk[i]) = st[i];
            }
            __syncthreads();
        }
#pragma unroll
        for (int i = 0; i < 2; ++i)
#pragma unroll
            for (int j = 0; j < 2; ++j)
                wmma::store_matrix_sync(&Sf[(mrow0 + i * 16) * QLD + ngq + j * 16],
                                        acc[i][j], QLD, wmma::mem_row_major);
        __syncthreads();

        // ---- bias + q-scale + convert -> qkv fp16 (aliases WB; pads unneeded) ----
        for (int t = tid; t < 49 * 192; t += 384) {
            int r = t / 192, cc = t % 192;
            int hh = cc / 96, c2 = cc % 96, which = c2 >> 5, d = c2 & 31;
            float vv = Sf[r * QLD + cc] + par[which * CDIM + (h0 + hh) * HDIM + d];
            if (which == 0) vv *= SCALE_Q;
            qkv[hh * 7680 + which * 2560 + r * KVLD + d] = __float2half_rn(vv);
        }
        __syncthreads();

        // ---- S = q @ k^T : 32 tiles over 12 warps ----
        for (int t = wp; t < 32; t += 12) {
            int hh = t >> 4, mi = (t >> 2) & 3, nj = t & 3;
            const __half* qh = qkv + hh * 7680;
            const __half* kh = qh + 2560;
            wmma::fragment<wmma::accumulator, 16, 16, 16, float> sacc;
            wmma::fill_fragment(sacc, 0.0f);
#pragma unroll
            for (int ks = 0; ks < 2; ++ks) {
                wmma::fragment<wmma::matrix_a, 16, 16, 16, __half, wmma::row_major> a1;
                wmma::fragment<wmma::matrix_b, 16, 16, 16, __half, wmma::col_major> b1;
                wmma::load_matrix_sync(a1, &qh[mi * 16 * KVLD + ks * 16], KVLD);
                wmma::load_matrix_sync(b1, &kh[nj * 16 * KVLD + ks * 16], KVLD);
                wmma::mma_sync(sacc, a1, b1, sacc);
            }
            wmma::store_matrix_sync(&Sf[hh * 4352 + mi * 16 * SLD + nj * 16],
                                    sacc, SLD, wmma::mem_row_major);
        }
        __syncthreads();

        // ---- softmax (+rpb+mask, lamb rescale) -> Sh fp16; zero pads ----
        for (int i2 = wp; i2 < 128; i2 += 12) {
            int hh = i2 >> 6, i = i2 & 63;
            __half* ShH = Sh + hh * 4608;
            if (i < NTOK) {
                const float lam1 = 1.0f + par[1536 + h0 + hh];
                const float invn = 1.0f / (float)NTOK;
                const __half* rbh = rb + (h0 + hh) * 169;
                const int i7 = i / 7, im = i - i7 * 7;
                const int j0 = l, j1 = l + 32;
                const int r0 = (i7 - j0 / 7 + 6) * 13 + (im - j0 % 7 + 6);
                float s0 = Sf[hh * 4352 + i * SLD + j0] + __half2float(rbh[r0]) + ms[i * 50 + j0];
                float s1 = -1e30f;
                if (j1 < NTOK) {
                    const int r1 = (i7 - j1 / 7 + 6) * 13 + (im - j1 % 7 + 6);
                    s1 = Sf[hh * 4352 + i * SLD + j1] + __half2float(rbh[r1]) + ms[i * 50 + j1];
                }
                float mx = fmaxf(s0, s1);
#pragma unroll
                for (int off = 16; off > 0; off >>= 1)
                    mx = fmaxf(mx, __shfl_xor_sync(0xffffffffu, mx, off));
                float e0 = __expf(s0 - mx);
                float e1 = (j1 < NTOK) ? __expf(s1 - mx) : 0.0f;
                float sm = e0 + e1;
#pragma unroll
                for (int off = 16; off > 0; off >>= 1)
                    sm += __shfl_xor_sync(0xffffffffu, sm, off);
                const float inv = 1.0f / sm;
                ShH[i * SHLD + j0] = __float2half_rn(invn + (e0 * inv - invn) * lam1);
                ShH[i * SHLD + j1] = (j1 < NTOK)
                    ? __float2half_rn(invn + (e1 * inv - invn) * lam1)
                    : __float2half_rn(0.0f);
            } else {
                ShH[i * SHLD + l]      = __float2half_rn(0.0f);
                ShH[i * SHLD + l + 32] = __float2half_rn(0.0f);
            }
        }
        __syncthreads();

        // ---- O = attn @ v : 16 tiles over 12 warps ----
        for (int t = wp; t < 16; t += 12) {
            int hh = t >> 3, mi = (t >> 1) & 3, nj = t & 1;
            const __half* ShH = Sh + hh * 4608;
            const __half* vhh = qkv + hh * 7680 + 5120;
            wmma::fragment<wmma::accumulator, 16, 16, 16, float> oacc;
            wmma::fill_fragment(oacc, 0.0f);
#pragma unroll
            for (int ks = 0; ks < 4; ++ks) {
                wmma::fragment<wmma::matrix_a, 16, 16, 16, __half, wmma::row_major> a1;
                wmma::fragment<wmma::matrix_b, 16, 16, 16, __half, wmma::row_major> b1;
                wmma::load_matrix_sync(a1, &ShH[mi * 16 * SHLD + ks * 16], SHLD);
                wmma::load_matrix_sync(b1, &vhh[ks * 16 * KVLD + nj * 16], KVLD);
                wmma::mma_sync(oacc, a1, b1, oacc);
            }
            wmma::store_matrix_sync(&Sf[hh * 4352 + mi * 16 * SLD + nj * 16],
                                    oacc, SLD, wmma::mem_row_major);
        }
        __syncthreads();

        // ---- convert O -> Oh ----
        for (int t = tid; t < 49 * 64; t += 384) {
            int r = t >> 6, cc = t & 63, hh = cc >> 5, d = cc & 31;
            Oh[r * XLD + (h0 + hh) * HDIM + d] = __float2half_rn(Sf[hh * 4352 + r * SLD + d]);
        }
        __syncthreads();
    }

    // =============== proj: out = Oh @ proj_w^T + b (hi/lo staged) ===============
    const int np = (wp >> 1) * 16;   // 16-col tile within 96-col p-chunk
    for (int p = 0; p < 4; ++p) {
        wmma::fragment<wmma::accumulator, 16, 16, 16, float> acc2[2];
        wmma::fill_fragment(acc2[0], 0.0f);
        wmma::fill_fragment(acc2[1], 0.0f);

        // prologue: stage chunk 0 (hi 96x64 + lo 96x64 = 1536 int4, 4/thread)
        int4 st[4];
#pragma unroll
        for (int i = 0; i < 4; ++i) {
            int v = tid + i * 384;
            int sel = (v >= 768), v2 = v - sel * 768;
            int j = v2 >> 3, k8 = (v2 & 7) << 3;
            st[i] = *(const int4*)((sel ? g_wpj_l : g_wpj_h)
                                   + (size_t)(p * 96 + j) * CDIM + k8);
        }
#pragma unroll
        for (int i = 0; i < 4; ++i) {
            int v = tid + i * 384;
            int sel = (v >= 768), v2 = v - sel * 768;
            int j = v2 >> 3, k8 = (v2 & 7) << 3;
            *(int4*)(WB + sel * PLOFF + j * WLD + k8) = st[i];
        }
        __syncthreads();

        for (int c = 0; c < 6; ++c) {
            if (c < 5) {
#pragma unroll
                for (int i = 0; i < 4; ++i) {
                    int v = tid + i * 384;
                    int sel = (v >= 768), v2 = v - sel * 768;
                    int j = v2 >> 3, k8 = (v2 & 7) << 3;
                    st[i] = *(const int4*)((sel ? g_wpj_l : g_wpj_h)
                                           + (size_t)(p * 96 + j) * CDIM + (c + 1) * 64 + k8);
                }
            }
            const __half* Wc = WB + (c & 1) * WBUF;
#pragma unroll
            for (int ks = 0; ks < 4; ++ks) {
                wmma::fragment<wmma::matrix_a, 16, 16, 16, __half, wmma::row_major> a0, a1;
                wmma::load_matrix_sync(a0, &Oh[mrow0 * XLD + c * 64 + ks * 16], XLD);
                wmma::load_matrix_sync(a1, &Oh[(mrow0 + 16) * XLD + c * 64 + ks * 16], XLD);
                wmma::fragment<wmma::matrix_b, 16, 16, 16, __half, wmma::col_major> bh, bl;
                wmma::load_matrix_sync(bh, &Wc[np * WLD + ks * 16], WLD);
                wmma::load_matrix_sync(bl, &Wc[PLOFF + np * WLD + ks * 16], WLD);
                wmma::mma_sync(acc2[0], a0, bh, acc2[0]);
                wmma::mma_sync(acc2[0], a0, bl, acc2[0]);
                wmma::mma_sync(acc2[1], a1, bh, acc2[1]);
                wmma::mma_sync(acc2[1], a1, bl, acc2[1]);
            }
            if (c < 5) {
#pragma unroll
                for (int i = 0; i < 4; ++i) {
                    int v = tid + i * 384;
                    int sel = (v >= 768), v2 = v - sel * 768;
                    int j = v2 >> 3, k8 = (v2 & 7) << 3;
                    *(int4*)(WB + ((c + 1) & 1) * WBUF + sel * PLOFF + j * WLD + k8) = st[i];
                }
            }
            __syncthreads();
        }

        wmma::store_matrix_sync(&Sf[mrow0 * PQLD + np], acc2[0], PQLD, wmma::mem_row_major);
        wmma::store_matrix_sync(&Sf[(mrow0 + 16) * PQLD + np], acc2[1], PQLD, wmma::mem_row_major);
        __syncthreads();

        for (int t = tid; t < 49 * 96; t += 384) {
            int r = t / 96, cc = t % 96;
            out[((size_t)w * NTOK + r) * CDIM + p * 96 + cc] = Sf[r * PQLD + cc] + par[1152 + p * 96 + cc];
        }
        __syncthreads();
    }
}

// ---------------------------------------------------------------------------
extern "C" void kernel_launch(void* const* d_in, const int* in_sizes, int n_in,
                              void* d_out, int out_size)
{
    const float *x = 0, *mask = 0, *qkv_w = 0, *qkv_b = 0;
    const float *proj_w = 0, *proj_b = 0, *rpb = 0, *lamb = 0;

    for (int i = 0; i < n_in; ++i) {
        const float* p = (const float*)d_in[i];
        switch (in_sizes[i]) {
            case 77070336: x      = p; break;
            case 2458624:  mask   = p; break;
            case 442368:   qkv_w  = p; break;
            case 1152:     qkv_b  = p; break;
            case 147456:   proj_w = p; break;
            case 384:      proj_b = p; break;
            case 2028:     rpb    = p; break;
            case 12:       lamb   = p; break;
            default: break;
        }
    }
    if (!x || !mask || !qkv_w || !qkv_b || !proj_w || !proj_b || !rpb || !lamb) {
        x      = (const float*)d_in[0];
        mask   = (const float*)d_in[1];
        qkv_w  = (const float*)d_in[2];
        qkv_b  = (const float*)d_in[3];
        proj_w = (const float*)d_in[4];
        proj_b = (const float*)d_in[5];
        rpb    = (const float*)d_in[6];
        lamb   = (const float*)d_in[7];
    }

    prep_qkv_w<<<(NHEADS * 96 * CDIM + 255) / 256, 256>>>(qkv_w);
    prep_proj_w<<<(CDIM * CDIM + 255) / 256, 256>>>(proj_w);

    cudaFuncSetAttribute(winattn_kernel,
                         cudaFuncAttributeMaxDynamicSharedMemorySize, SMEM_BYTES);
    winattn_kernel<<<B_WIN, 384, SMEM_BYTES>>>(
        x, mask, qkv_b, proj_b, rpb, lamb, (float*)d_out);
}